// round 5
// baseline (speedup 1.0000x reference)
#include <cuda_runtime.h>
#include <cuda_fp16.h>
#include <math.h>
#include <stdint.h>

#define BB 4
#define SS 4096
#define CCH 128
#define HIDN 256
#define NROWS (BB*SS)      /* 16384 */
#define NCHUNK 32          /* one stat chunk per 128-row score tile */

/* ------------ scratch (device globals: allocation-free rule) ------------- */
__device__ float g_t   [NROWS*CCH];
__device__ float g_xl  [NROWS*CCH];
__device__ float g_q   [NROWS*CCH];
__device__ float g_k   [NROWS*CCH];
__device__ float g_v   [NROWS*CCH];
__device__ float g_vT  [NROWS*CCH];
__device__ float g_y   [NROWS*CCH];
__device__ float g_ao  [NROWS*CCH];
__device__ float g_fin [NROWS*CCH];
__device__ float g_h   [NROWS*HIDN];
__device__ __half g_scoresh[(size_t)BB*SS*SS];   /* 134 MB fp16 scores */
__device__ float g_pm  [NCHUNK*NROWS];
__device__ float g_ps  [NCHUNK*NROWS];
__device__ float g_off [NROWS];
__device__ float g_wqT [CCH*CCH];
__device__ float g_wkT [CCH*CCH];
__device__ float g_wvT [CCH*CCH];
__device__ float g_woT [CCH*CCH];
__device__ float g_w1T [CCH*HIDN];
__device__ float g_w2T [CCH*HIDN];

/* ------------------------- fast exp (FFMA-only) -------------------------- */
__device__ __forceinline__ float fexp(float x) {
    x = fmaxf(x, -80.0f);
    float t = x * 1.4426950408889634f;
    float k = rintf(t);
    float f = fmaf(k, -0.693359375f, x);
    f = fmaf(k, 2.12194440e-4f, f);
    float p = fmaf(f, 8.3333333e-3f, 4.1666667e-2f);
    p = fmaf(p, f, 1.6666667e-1f);
    p = fmaf(p, f, 5.0e-1f);
    p = fmaf(p, f, 1.0f);
    p = fmaf(p, f, 1.0f);
    int ki = (int)k;
    float sc = __int_as_float((ki + 127) << 23);
    return p * sc;
}

__device__ __forceinline__ float gelu_exact(float v) {
    return 0.5f * v * (1.0f + erff(v * 0.70710678118654752f));
}

__device__ __forceinline__ float tf32r(float x) {
    uint32_t u;
    asm("cvt.rna.tf32.f32 %0, %1;" : "=r"(u) : "f"(x));
    return __uint_as_float(u);
}

__device__ __forceinline__ void mma_tf32_16n8k8(
    float* d, uint32_t a0, uint32_t a1, uint32_t a2, uint32_t a3,
    uint32_t b0, uint32_t b1)
{
    asm volatile(
        "mma.sync.aligned.m16n8k8.row.col.f32.tf32.tf32.f32 "
        "{%0,%1,%2,%3}, {%4,%5,%6,%7}, {%8,%9}, {%0,%1,%2,%3};"
        : "+f"(d[0]), "+f"(d[1]), "+f"(d[2]), "+f"(d[3])
        : "r"(a0), "r"(a1), "r"(a2), "r"(a3), "r"(b0), "r"(b1));
}

/* merge two online-softmax partials (m1,l1) <- (m1,l1) + (m2,l2) */
__device__ __forceinline__ void olmerge(float& m, float& l, float om, float ol) {
    float nm = fmaxf(m, om);
    l = l * fexp(m - nm) + ol * fexp(om - nm);
    m = nm;
}

/* --------------------- generic 2D transpose per batch -------------------- */
__global__ __launch_bounds__(1024) void transpose_k(
    const float* __restrict__ src, float* __restrict__ dst, int R, int Cc)
{
    __shared__ float tile[32][33];
    size_t zo = (size_t)blockIdx.z * R * Cc;
    int c0 = blockIdx.x * 32, r0 = blockIdx.y * 32;
    int x = threadIdx.x, y = threadIdx.y;
    tile[y][x] = src[zo + (size_t)(r0 + y) * Cc + c0 + x];
    __syncthreads();
    dst[zo + (size_t)(c0 + y) * R + r0 + x] = tile[x][y];
}

/* ----------------------------- LayerNorm --------------------------------- */
__global__ __launch_bounds__(256) void ln_k(
    const float* __restrict__ in, const float* __restrict__ w,
    const float* __restrict__ b, float* __restrict__ out)
{
    int row  = blockIdx.x * 8 + (threadIdx.x >> 5);
    int lane = threadIdx.x & 31;
    size_t base = (size_t)row * CCH + lane * 4;
    float4 v = *(const float4*)&in[base];
    float s = v.x + v.y + v.z + v.w;
    #pragma unroll
    for (int o = 16; o > 0; o >>= 1) s += __shfl_xor_sync(0xffffffffu, s, o);
    float mu = s * (1.0f / 128.0f);
    float dx = v.x - mu, dy = v.y - mu, dz = v.z - mu, dw = v.w - mu;
    float q = dx*dx + dy*dy + dz*dz + dw*dw;
    #pragma unroll
    for (int o = 16; o > 0; o >>= 1) q += __shfl_xor_sync(0xffffffffu, q, o);
    float rstd = rsqrtf(q * (1.0f / 128.0f) + 1e-5f);
    float4 wv = *(const float4*)&w[lane * 4];
    float4 bv = *(const float4*)&b[lane * 4];
    float4 o4;
    o4.x = dx * rstd * wv.x + bv.x;
    o4.y = dy * rstd * wv.y + bv.y;
    o4.z = dz * rstd * wv.z + bv.z;
    o4.w = dw * rstd * wv.w + bv.w;
    *(float4*)&out[base] = o4;
}

/* ------------------ tf32 mma.sync GEMM: D = A @ B^T ----------------------- */
/* A row-major [M,K], B row-major [N,K]. Tile 128x128, BK=32 double-buffered.
 * 256 threads = 8 warps (4M x 2N); warp tile 32x64; m16n8k8 tf32.
 * AMODE: 0 = float A; 1 = half A with fexp(a - off[k]).
 * EPI:   0 alpha; 1 +bias; 2 +bias+res; 3 gelu(+bias); 4 gelu(+bias)+res;
 *        5 half output + per-column online softmax partial stats.
 */
#define LDA 36
#define ABUF (128*LDA)
#define GEMM_SMEM (4*ABUF*4)      /* 73728 bytes */

template<int AMODE, int EPI>
__global__ __launch_bounds__(256, 1) void gemm_mma(
    const void* __restrict__ A, const float* __restrict__ Bm,
    const float* __restrict__ bias, const float* __restrict__ res,
    void* __restrict__ Cout,
    int N, int K,
    long long sA, long long sB, long long sC,
    const float* __restrict__ off, int sOff, float alpha,
    float* __restrict__ pm, float* __restrict__ ps)
{
    extern __shared__ float sm[];
    float* As[2] = { sm,            sm + ABUF };
    float* Bs[2] = { sm + 2*ABUF,   sm + 3*ABUF };

    int t = threadIdx.x;
    int wid = t >> 5, lane = t & 31;
    int wm = wid & 3, wn = wid >> 2;
    int z = blockIdx.z;
    const float*  Abf = (AMODE == 0) ? (const float*)A + (size_t)z * sA : nullptr;
    const __half* Abh = (AMODE == 1) ? (const __half*)A + (size_t)z * sA : nullptr;
    const float* Bb = Bm + (size_t)z * sB;
    const float* Rb = (EPI == 2 || EPI == 4) ? res + (size_t)z * sC : nullptr;
    const float* offb = (AMODE == 1) ? off + (size_t)z * sOff : nullptr;
    int m0 = blockIdx.y * 128;
    int n0 = blockIdx.x * 128;

    float acc[2][8][4];
    #pragma unroll
    for (int mt = 0; mt < 2; mt++)
        #pragma unroll
        for (int nt = 0; nt < 8; nt++)
            #pragma unroll
            for (int e = 0; e < 4; e++) acc[mt][nt][e] = 0.0f;

    int nch = K >> 5;

    float4 ra[4], rb[4];
    auto ldg_chunk = [&](int c) {
        int k0 = c << 5;
        #pragma unroll
        for (int i = 0; i < 4; i++) {
            int idx = i * 256 + t;
            int r = idx >> 3, c4 = idx & 7;
            float4 v;
            if (AMODE == 1) {
                uint2 raw = *(const uint2*)&Abh[(size_t)(m0 + r) * K + k0 + c4 * 4];
                __half2 h01 = *(__half2*)&raw.x;
                __half2 h23 = *(__half2*)&raw.y;
                int kk = k0 + c4 * 4;
                v.x = fexp(__low2float(h01)  - __ldg(offb + kk + 0));
                v.y = fexp(__high2float(h01) - __ldg(offb + kk + 1));
                v.z = fexp(__low2float(h23)  - __ldg(offb + kk + 2));
                v.w = fexp(__high2float(h23) - __ldg(offb + kk + 3));
            } else {
                v = *(const float4*)&Abf[(size_t)(m0 + r) * K + k0 + c4 * 4];
            }
            v.x = tf32r(v.x); v.y = tf32r(v.y); v.z = tf32r(v.z); v.w = tf32r(v.w);
            ra[i] = v;
            float4 w4 = *(const float4*)&Bb[(size_t)(n0 + r) * K + k0 + c4 * 4];
            w4.x = tf32r(w4.x); w4.y = tf32r(w4.y); w4.z = tf32r(w4.z); w4.w = tf32r(w4.w);
            rb[i] = w4;
        }
    };
    auto st_chunk = [&](int buf) {
        #pragma unroll
        for (int i = 0; i < 4; i++) {
            int idx = i * 256 + t;
            int r = idx >> 3, c4 = idx & 7;
            *(float4*)&As[buf][r * LDA + c4 * 4] = ra[i];
            *(float4*)&Bs[buf][r * LDA + c4 * 4] = rb[i];
        }
    };

    ldg_chunk(0);
    st_chunk(0);
    __syncthreads();

    int aR = wm * 32 + (lane >> 2);
    int bR = wn * 64 + (lane >> 2);
    int kc0 = lane & 3;

    for (int c = 0; c < nch; c++) {
        if (c + 1 < nch) ldg_chunk(c + 1);
        const float* Ap = As[c & 1];
        const float* Bp = Bs[c & 1];
        #pragma unroll
        for (int s = 0; s < 4; s++) {
            int kc = s * 8 + kc0;
            uint32_t af[2][4];
            #pragma unroll
            for (int mt = 0; mt < 2; mt++) {
                const float* r0p = Ap + (aR + mt * 16) * LDA;
                const float* r1p = Ap + (aR + mt * 16 + 8) * LDA;
                af[mt][0] = __float_as_uint(r0p[kc]);
                af[mt][1] = __float_as_uint(r1p[kc]);
                af[mt][2] = __float_as_uint(r0p[kc + 4]);
                af[mt][3] = __float_as_uint(r1p[kc + 4]);
            }
            #pragma unroll
            for (int nt = 0; nt < 8; nt++) {
                const float* bp = Bp + (bR + nt * 8) * LDA;
                uint32_t b0 = __float_as_uint(bp[kc]);
                uint32_t b1 = __float_as_uint(bp[kc + 4]);
                #pragma unroll
                for (int mt = 0; mt < 2; mt++)
                    mma_tf32_16n8k8(acc[mt][nt],
                                    af[mt][0], af[mt][1], af[mt][2], af[mt][3],
                                    b0, b1);
            }
        }
        if (c + 1 < nch) {
            st_chunk((c + 1) & 1);
            __syncthreads();
        }
    }

    /* ------------------------------ epilogue ----------------------------- */
    int rbase = m0 + wm * 32 + (lane >> 2);
    int cbase = n0 + wn * 64 + (lane & 3) * 2;

    if (EPI == 5) {
        /* half output + per-column softmax partials over this tile */
        __half* Cb = (__half*)Cout + (size_t)z * sC;
        #pragma unroll
        for (int mt = 0; mt < 2; mt++) {
            #pragma unroll
            for (int half = 0; half < 2; half++) {
                int row = rbase + mt * 16 + half * 8;
                size_t rowo = (size_t)row * N;
                #pragma unroll
                for (int nt = 0; nt < 8; nt++) {
                    int col = cbase + nt * 8;
                    __half h0 = __float2half_rn(acc[mt][nt][half*2+0] * alpha);
                    __half h1 = __float2half_rn(acc[mt][nt][half*2+1] * alpha);
                    /* keep the rounded values for stats */
                    acc[mt][nt][half*2+0] = __half2float(h0);
                    acc[mt][nt][half*2+1] = __half2float(h1);
                    __half2 h2; h2.x = h0; h2.y = h1;
                    *(__half2*)&Cb[rowo + col] = h2;
                }
            }
        }
        __syncthreads();                     /* mainloop smem now reusable */
        float* smm = sm;                     /* [4][132] */
        float* sml = sm + 4 * 132;
        #pragma unroll
        for (int nt = 0; nt < 8; nt++) {
            #pragma unroll
            for (int e = 0; e < 2; e++) {
                float m = -1e30f, l = 0.0f;
                #pragma unroll
                for (int mt = 0; mt < 2; mt++)
                    #pragma unroll
                    for (int half = 0; half < 2; half++) {
                        float v = acc[mt][nt][half*2+e];
                        if (v <= m) l += fexp(v - m);
                        else { l = l * fexp(m - v) + 1.0f; m = v; }
                    }
                #pragma unroll
                for (int o = 4; o < 32; o <<= 1) {
                    float om = __shfl_xor_sync(0xffffffffu, m, o);
                    float ol = __shfl_xor_sync(0xffffffffu, l, o);
                    olmerge(m, l, om, ol);
                }
                if ((lane >> 2) == 0) {
                    int cl = wn * 64 + nt * 8 + (lane & 3) * 2 + e;
                    smm[wm * 132 + cl] = m;
                    sml[wm * 132 + cl] = l;
                }
            }
        }
        __syncthreads();
        if (t < 128) {
            float m = smm[t], l = sml[t];
            #pragma unroll
            for (int w = 1; w < 4; w++)
                olmerge(m, l, smm[w * 132 + t], sml[w * 132 + t]);
            size_t o = ((size_t)blockIdx.y * BB + z) * SS + n0 + t;
            pm[o] = m;
            ps[o] = l;
        }
        return;
    }

    float* Cb = (float*)Cout + (size_t)z * sC;
    #pragma unroll
    for (int mt = 0; mt < 2; mt++) {
        #pragma unroll
        for (int half = 0; half < 2; half++) {
            int row = rbase + mt * 16 + half * 8;
            size_t rowo = (size_t)row * N;
            #pragma unroll
            for (int nt = 0; nt < 8; nt++) {
                int col = cbase + nt * 8;
                float u0 = acc[mt][nt][half * 2 + 0] * alpha;
                float u1 = acc[mt][nt][half * 2 + 1] * alpha;
                if (EPI >= 1) {
                    u0 += __ldg(&bias[col]);
                    u1 += __ldg(&bias[col + 1]);
                }
                if (EPI == 3 || EPI == 4) {
                    u0 = gelu_exact(u0);
                    u1 = gelu_exact(u1);
                }
                if (EPI == 2 || EPI == 4) {
                    u0 += Rb[rowo + col];
                    u1 += Rb[rowo + col + 1];
                }
                float2 o2; o2.x = u0; o2.y = u1;
                *(float2*)&Cb[rowo + col] = o2;
            }
        }
    }
}

/* reduce partials -> off[j] = m + log(l) */
__global__ __launch_bounds__(256) void colreduce_k(
    const float* __restrict__ pm, const float* __restrict__ ps,
    float* __restrict__ off)
{
    int idx = blockIdx.x * 256 + threadIdx.x;
    float m = -1e30f;
    #pragma unroll
    for (int c = 0; c < NCHUNK; c++) m = fmaxf(m, pm[(size_t)c * NROWS + idx]);
    float l = 0.0f;
    #pragma unroll
    for (int c = 0; c < NCHUNK; c++)
        l += ps[(size_t)c * NROWS + idx] * fexp(pm[(size_t)c * NROWS + idx] - m);
    off[idx] = m + logf(l);
}

/* ------------------------------- launch ---------------------------------- */
static float* sym(const void* s) {
    void* p = nullptr;
    cudaGetSymbolAddress(&p, s);
    return (float*)p;
}

extern "C" void kernel_launch(void* const* d_in, const int* in_sizes, int n_in,
                              void* d_out, int out_size)
{
    const float* x    = (const float*)d_in[0];
    const float* ln1w = (const float*)d_in[1];
    const float* ln1b = (const float*)d_in[2];
    const float* wq   = (const float*)d_in[3];
    const float* bq   = (const float*)d_in[4];
    const float* wk   = (const float*)d_in[5];
    const float* bk   = (const float*)d_in[6];
    const float* wv   = (const float*)d_in[7];
    const float* bv   = (const float*)d_in[8];
    const float* wo   = (const float*)d_in[9];
    const float* bo   = (const float*)d_in[10];
    const float* ln2w = (const float*)d_in[11];
    const float* ln2b = (const float*)d_in[12];
    const float* w1   = (const float*)d_in[13];
    const float* b1   = (const float*)d_in[14];
    const float* w2   = (const float*)d_in[15];
    const float* b2   = (const float*)d_in[16];
    float* out = (float*)d_out;

    float* pt   = sym(g_t);
    float* pxl  = sym(g_xl);
    float* pq   = sym(g_q);
    float* pk   = sym(g_k);
    float* pv   = sym(g_v);
    float* pvT  = sym(g_vT);
    float* py   = sym(g_y);
    float* pao  = sym(g_ao);
    float* pfin = sym(g_fin);
    float* ph_  = sym(g_h);
    void*  psch = nullptr; cudaGetSymbolAddress(&psch, g_scoresh);
    float* ppm  = sym(g_pm);
    float* pps  = sym(g_ps);
    float* poff = sym(g_off);
    float* pwqT = sym(g_wqT);
    float* pwkT = sym(g_wkT);
    float* pwvT = sym(g_wvT);
    float* pwoT = sym(g_woT);
    float* pw1T = sym(g_w1T);
    float* pw2T = sym(g_w2T);

    cudaFuncSetAttribute(gemm_mma<0,1>, cudaFuncAttributeMaxDynamicSharedMemorySize, GEMM_SMEM);
    cudaFuncSetAttribute(gemm_mma<0,2>, cudaFuncAttributeMaxDynamicSharedMemorySize, GEMM_SMEM);
    cudaFuncSetAttribute(gemm_mma<0,3>, cudaFuncAttributeMaxDynamicSharedMemorySize, GEMM_SMEM);
    cudaFuncSetAttribute(gemm_mma<0,4>, cudaFuncAttributeMaxDynamicSharedMemorySize, GEMM_SMEM);
    cudaFuncSetAttribute(gemm_mma<0,5>, cudaFuncAttributeMaxDynamicSharedMemorySize, GEMM_SMEM);
    cudaFuncSetAttribute(gemm_mma<1,0>, cudaFuncAttributeMaxDynamicSharedMemorySize, GEMM_SMEM);

    dim3 tb(32, 32);
    const long long sSC = (long long)SS * CCH;
    const long long sS2 = (long long)SS * SS;

    /* x [B,C,S] -> t [B,S,C] */
    transpose_k<<<dim3(SS/32, CCH/32, BB), tb>>>(x, pt, CCH, SS);

    /* LN1 */
    ln_k<<<NROWS/8, 256>>>(pt, ln1w, ln1b, pxl);

    /* weight transposes (W[K,N] -> W^T[N,K]) */
    transpose_k<<<dim3(4, 4, 1), tb>>>(wq, pwqT, CCH, CCH);
    transpose_k<<<dim3(4, 4, 1), tb>>>(wk, pwkT, CCH, CCH);
    transpose_k<<<dim3(4, 4, 1), tb>>>(wv, pwvT, CCH, CCH);
    transpose_k<<<dim3(4, 4, 1), tb>>>(wo, pwoT, CCH, CCH);
    transpose_k<<<dim3(8, 4, 1), tb>>>(w1, pw1T, CCH, HIDN);
    transpose_k<<<dim3(4, 8, 1), tb>>>(w2, pw2T, HIDN, CCH);

    /* QKV projections */
    gemm_mma<0,1><<<dim3(1, NROWS/128, 1), 256, GEMM_SMEM>>>(pxl, pwqT, bq, nullptr, pq,
        CCH, CCH, 0, 0, 0, nullptr, 0, 1.0f, nullptr, nullptr);
    gemm_mma<0,1><<<dim3(1, NROWS/128, 1), 256, GEMM_SMEM>>>(pxl, pwkT, bk, nullptr, pk,
        CCH, CCH, 0, 0, 0, nullptr, 0, 1.0f, nullptr, nullptr);
    gemm_mma<0,1><<<dim3(1, NROWS/128, 1), 256, GEMM_SMEM>>>(pxl, pwvT, bv, nullptr, pv,
        CCH, CCH, 0, 0, 0, nullptr, 0, 1.0f, nullptr, nullptr);

    /* scores = 0.25 * q @ k^T -> fp16, with fused column-stat partials */
    gemm_mma<0,5><<<dim3(SS/128, SS/128, BB), 256, GEMM_SMEM>>>(pq, pk, nullptr, nullptr, psch,
        SS, CCH, sSC, sSC, sS2, nullptr, 0, 0.25f, ppm, pps);

    /* reduce partials to off */
    colreduce_k<<<NROWS/256, 256>>>(ppm, pps, poff);

    /* v -> vT per batch */
    transpose_k<<<dim3(CCH/32, SS/32, BB), tb>>>(pv, pvT, SS, CCH);

    /* ao = exp(scores - off) @ v (half A, exp on tile load) */
    gemm_mma<1,0><<<dim3(1, SS/128, BB), 256, GEMM_SMEM>>>(psch, pvT, nullptr, nullptr, pao,
        CCH, SS, sS2, sSC, sSC, poff, SS, 1.0f, nullptr, nullptr);

    /* y = ao @ wo + bo + t */
    gemm_mma<0,2><<<dim3(1, NROWS/128, 1), 256, GEMM_SMEM>>>(pao, pwoT, bo, pt, py,
        CCH, CCH, 0, 0, 0, nullptr, 0, 1.0f, nullptr, nullptr);

    /* LN2 */
    ln_k<<<NROWS/8, 256>>>(py, ln2w, ln2b, pxl);

    /* h = gelu(ln2 @ w1 + b1) */
    gemm_mma<0,3><<<dim3(HIDN/128, NROWS/128, 1), 256, GEMM_SMEM>>>(pxl, pw1T, b1, nullptr, ph_,
        HIDN, CCH, 0, 0, 0, nullptr, 0, 1.0f, nullptr, nullptr);

    /* fin = gelu(h @ w2 + b2) + y */
    gemm_mma<0,4><<<dim3(1, NROWS/128, 1), 256, GEMM_SMEM>>>(ph_, pw2T, b2, py, pfin,
        CCH, HIDN, 0, 0, 0, nullptr, 0, 1.0f, nullptr, nullptr);

    /* fin [B,S,C] -> out [B,C,H,W] */
    transpose_k<<<dim3(CCH/32, SS/32, BB), tb>>>(pfin, out, SS, CCH);
}

// round 6
// speedup vs baseline: 1.7010x; 1.7010x over previous
#include <cuda_runtime.h>
#include <cuda_fp16.h>
#include <math.h>
#include <stdint.h>

#define BB 4
#define SS 4096
#define CCH 128
#define HIDN 256
#define NROWS (BB*SS)      /* 16384 */
#define NCHUNK 16
#define ROWS_PER_CHUNK (SS/NCHUNK)  /* 256 */

/* ------------ scratch (device globals: allocation-free rule) ------------- */
__device__ float g_t   [NROWS*CCH];
__device__ float g_xl  [NROWS*CCH];
__device__ float g_q   [NROWS*CCH];
__device__ float g_k   [NROWS*CCH];
__device__ float g_v   [NROWS*CCH];
__device__ float g_vT  [NROWS*CCH];
__device__ float g_y   [NROWS*CCH];
__device__ float g_ao  [NROWS*CCH];
__device__ float g_fin [NROWS*CCH];
__device__ float g_h   [NROWS*HIDN];
__device__ __half g_scoresh[(size_t)BB*SS*SS];   /* 134 MB fp16 scores */
__device__ float g_pm  [NCHUNK*NROWS];
__device__ float g_ps  [NCHUNK*NROWS];
__device__ float g_off [NROWS];
__device__ float g_wqT [CCH*CCH];
__device__ float g_wkT [CCH*CCH];
__device__ float g_wvT [CCH*CCH];
__device__ float g_woT [CCH*CCH];
__device__ float g_w1T [CCH*HIDN];
__device__ float g_w2T [CCH*HIDN];

/* ------------------------- fast exp (FFMA-only) -------------------------- */
__device__ __forceinline__ float fexp(float x) {
    x = fmaxf(x, -80.0f);
    float t = x * 1.4426950408889634f;
    float k = rintf(t);
    float f = fmaf(k, -0.693359375f, x);
    f = fmaf(k, 2.12194440e-4f, f);
    float p = fmaf(f, 8.3333333e-3f, 4.1666667e-2f);
    p = fmaf(p, f, 1.6666667e-1f);
    p = fmaf(p, f, 5.0e-1f);
    p = fmaf(p, f, 1.0f);
    p = fmaf(p, f, 1.0f);
    int ki = (int)k;
    float sc = __int_as_float((ki + 127) << 23);
    return p * sc;
}

__device__ __forceinline__ float gelu_exact(float v) {
    return 0.5f * v * (1.0f + erff(v * 0.70710678118654752f));
}

__device__ __forceinline__ float tf32r(float x) {
    uint32_t u;
    asm("cvt.rna.tf32.f32 %0, %1;" : "=r"(u) : "f"(x));
    return __uint_as_float(u);
}

__device__ __forceinline__ void mma_tf32_16n8k8(
    float* d, uint32_t a0, uint32_t a1, uint32_t a2, uint32_t a3,
    uint32_t b0, uint32_t b1)
{
    asm volatile(
        "mma.sync.aligned.m16n8k8.row.col.f32.tf32.tf32.f32 "
        "{%0,%1,%2,%3}, {%4,%5,%6,%7}, {%8,%9}, {%0,%1,%2,%3};"
        : "+f"(d[0]), "+f"(d[1]), "+f"(d[2]), "+f"(d[3])
        : "r"(a0), "r"(a1), "r"(a2), "r"(a3), "r"(b0), "r"(b1));
}

/* --------------------- generic 2D transpose per batch -------------------- */
__global__ __launch_bounds__(1024) void transpose_k(
    const float* __restrict__ src, float* __restrict__ dst, int R, int Cc)
{
    __shared__ float tile[32][33];
    size_t zo = (size_t)blockIdx.z * R * Cc;
    int c0 = blockIdx.x * 32, r0 = blockIdx.y * 32;
    int x = threadIdx.x, y = threadIdx.y;
    tile[y][x] = src[zo + (size_t)(r0 + y) * Cc + c0 + x];
    __syncthreads();
    dst[zo + (size_t)(c0 + y) * R + r0 + x] = tile[x][y];
}

/* ----------------------------- LayerNorm --------------------------------- */
__global__ __launch_bounds__(256) void ln_k(
    const float* __restrict__ in, const float* __restrict__ w,
    const float* __restrict__ b, float* __restrict__ out)
{
    int row  = blockIdx.x * 8 + (threadIdx.x >> 5);
    int lane = threadIdx.x & 31;
    size_t base = (size_t)row * CCH + lane * 4;
    float4 v = *(const float4*)&in[base];
    float s = v.x + v.y + v.z + v.w;
    #pragma unroll
    for (int o = 16; o > 0; o >>= 1) s += __shfl_xor_sync(0xffffffffu, s, o);
    float mu = s * (1.0f / 128.0f);
    float dx = v.x - mu, dy = v.y - mu, dz = v.z - mu, dw = v.w - mu;
    float q = dx*dx + dy*dy + dz*dz + dw*dw;
    #pragma unroll
    for (int o = 16; o > 0; o >>= 1) q += __shfl_xor_sync(0xffffffffu, q, o);
    float rstd = rsqrtf(q * (1.0f / 128.0f) + 1e-5f);
    float4 wv = *(const float4*)&w[lane * 4];
    float4 bv = *(const float4*)&b[lane * 4];
    float4 o4;
    o4.x = dx * rstd * wv.x + bv.x;
    o4.y = dy * rstd * wv.y + bv.y;
    o4.z = dz * rstd * wv.z + bv.z;
    o4.w = dw * rstd * wv.w + bv.w;
    *(float4*)&out[base] = o4;
}

/* ------------------ tf32 mma.sync GEMM: D = A @ B^T ----------------------- */
/* A row-major [M,K], B row-major [N,K]. Tile 128x128, BK=32 double-buffered.
 * 256 threads = 8 warps (4M x 2N); warp tile 32x64; m16n8k8 tf32.
 * AMODE: 0 = float A; 1 = half A with fexp(a - off[k]).
 * EPI:   0 alpha; 1 +bias; 2 +bias+res; 3 gelu(+bias); 4 gelu(+bias)+res;
 *        5 alpha + fp16 store (register-light).
 */
#define LDA 36
#define ABUF (128*LDA)
#define GEMM_SMEM (4*ABUF*4)      /* 73728 bytes */

template<int AMODE, int EPI>
__global__ __launch_bounds__(256, 1) void gemm_mma(
    const void* __restrict__ A, const float* __restrict__ Bm,
    const float* __restrict__ bias, const float* __restrict__ res,
    void* __restrict__ Cout,
    int N, int K,
    long long sA, long long sB, long long sC,
    const float* __restrict__ off, int sOff, float alpha)
{
    extern __shared__ float sm[];
    float* As[2] = { sm,            sm + ABUF };
    float* Bs[2] = { sm + 2*ABUF,   sm + 3*ABUF };

    int t = threadIdx.x;
    int wid = t >> 5, lane = t & 31;
    int wm = wid & 3, wn = wid >> 2;
    int z = blockIdx.z;
    const float*  Abf = (AMODE == 0) ? (const float*)A + (size_t)z * sA : nullptr;
    const __half* Abh = (AMODE == 1) ? (const __half*)A + (size_t)z * sA : nullptr;
    const float* Bb = Bm + (size_t)z * sB;
    const float* Rb = (EPI == 2 || EPI == 4) ? res + (size_t)z * sC : nullptr;
    const float* offb = (AMODE == 1) ? off + (size_t)z * sOff : nullptr;
    int m0 = blockIdx.y * 128;
    int n0 = blockIdx.x * 128;

    float acc[2][8][4];
    #pragma unroll
    for (int mt = 0; mt < 2; mt++)
        #pragma unroll
        for (int nt = 0; nt < 8; nt++)
            #pragma unroll
            for (int e = 0; e < 4; e++) acc[mt][nt][e] = 0.0f;

    int nch = K >> 5;

    float4 ra[4], rb[4];
    auto ldg_chunk = [&](int c) {
        int k0 = c << 5;
        #pragma unroll
        for (int i = 0; i < 4; i++) {
            int idx = i * 256 + t;
            int r = idx >> 3, c4 = idx & 7;
            float4 v;
            if (AMODE == 1) {
                uint2 raw = *(const uint2*)&Abh[(size_t)(m0 + r) * K + k0 + c4 * 4];
                __half2 h01 = *(__half2*)&raw.x;
                __half2 h23 = *(__half2*)&raw.y;
                int kk = k0 + c4 * 4;
                v.x = fexp(__low2float(h01)  - __ldg(offb + kk + 0));
                v.y = fexp(__high2float(h01) - __ldg(offb + kk + 1));
                v.z = fexp(__low2float(h23)  - __ldg(offb + kk + 2));
                v.w = fexp(__high2float(h23) - __ldg(offb + kk + 3));
            } else {
                v = *(const float4*)&Abf[(size_t)(m0 + r) * K + k0 + c4 * 4];
            }
            v.x = tf32r(v.x); v.y = tf32r(v.y); v.z = tf32r(v.z); v.w = tf32r(v.w);
            ra[i] = v;
            float4 w4 = *(const float4*)&Bb[(size_t)(n0 + r) * K + k0 + c4 * 4];
            w4.x = tf32r(w4.x); w4.y = tf32r(w4.y); w4.z = tf32r(w4.z); w4.w = tf32r(w4.w);
            rb[i] = w4;
        }
    };
    auto st_chunk = [&](int buf) {
        #pragma unroll
        for (int i = 0; i < 4; i++) {
            int idx = i * 256 + t;
            int r = idx >> 3, c4 = idx & 7;
            *(float4*)&As[buf][r * LDA + c4 * 4] = ra[i];
            *(float4*)&Bs[buf][r * LDA + c4 * 4] = rb[i];
        }
    };

    ldg_chunk(0);
    st_chunk(0);
    __syncthreads();

    int aR = wm * 32 + (lane >> 2);
    int bR = wn * 64 + (lane >> 2);
    int kc0 = lane & 3;

    for (int c = 0; c < nch; c++) {
        if (c + 1 < nch) ldg_chunk(c + 1);
        const float* Ap = As[c & 1];
        const float* Bp = Bs[c & 1];
        #pragma unroll
        for (int s = 0; s < 4; s++) {
            int kc = s * 8 + kc0;
            uint32_t af[2][4];
            #pragma unroll
            for (int mt = 0; mt < 2; mt++) {
                const float* r0p = Ap + (aR + mt * 16) * LDA;
                const float* r1p = Ap + (aR + mt * 16 + 8) * LDA;
                af[mt][0] = __float_as_uint(r0p[kc]);
                af[mt][1] = __float_as_uint(r1p[kc]);
                af[mt][2] = __float_as_uint(r0p[kc + 4]);
                af[mt][3] = __float_as_uint(r1p[kc + 4]);
            }
            #pragma unroll
            for (int nt = 0; nt < 8; nt++) {
                const float* bp = Bp + (bR + nt * 8) * LDA;
                uint32_t b0 = __float_as_uint(bp[kc]);
                uint32_t b1 = __float_as_uint(bp[kc + 4]);
                #pragma unroll
                for (int mt = 0; mt < 2; mt++)
                    mma_tf32_16n8k8(acc[mt][nt],
                                    af[mt][0], af[mt][1], af[mt][2], af[mt][3],
                                    b0, b1);
            }
        }
        if (c + 1 < nch) {
            st_chunk((c + 1) & 1);
            __syncthreads();
        }
    }

    /* ------------------------------ epilogue ----------------------------- */
    int rbase = m0 + wm * 32 + (lane >> 2);
    int cbase = n0 + wn * 64 + (lane & 3) * 2;

    if (EPI == 5) {
        /* fp16 store, register-light */
        __half* Cb = (__half*)Cout + (size_t)z * sC;
        #pragma unroll
        for (int mt = 0; mt < 2; mt++) {
            #pragma unroll
            for (int hh = 0; hh < 2; hh++) {
                int row = rbase + mt * 16 + hh * 8;
                size_t rowo = (size_t)row * N;
                #pragma unroll
                for (int nt = 0; nt < 8; nt++) {
                    int col = cbase + nt * 8;
                    __half2 h2 = __floats2half2_rn(acc[mt][nt][hh*2+0] * alpha,
                                                   acc[mt][nt][hh*2+1] * alpha);
                    *(__half2*)&Cb[rowo + col] = h2;
                }
            }
        }
        return;
    }

    float* Cb = (float*)Cout + (size_t)z * sC;
    #pragma unroll
    for (int mt = 0; mt < 2; mt++) {
        #pragma unroll
        for (int hh = 0; hh < 2; hh++) {
            int row = rbase + mt * 16 + hh * 8;
            size_t rowo = (size_t)row * N;
            #pragma unroll
            for (int nt = 0; nt < 8; nt++) {
                int col = cbase + nt * 8;
                float u0 = acc[mt][nt][hh * 2 + 0] * alpha;
                float u1 = acc[mt][nt][hh * 2 + 1] * alpha;
                if (EPI >= 1) {
                    u0 += __ldg(&bias[col]);
                    u1 += __ldg(&bias[col + 1]);
                }
                if (EPI == 3 || EPI == 4) {
                    u0 = gelu_exact(u0);
                    u1 = gelu_exact(u1);
                }
                if (EPI == 2 || EPI == 4) {
                    u0 += Rb[rowo + col];
                    u1 += Rb[rowo + col + 1];
                }
                float2 o2; o2.x = u0; o2.y = u1;
                *(float2*)&Cb[rowo + col] = o2;
            }
        }
    }
}

/* ------------- column (query-axis) softmax stats on fp16 scores ---------- */
__global__ __launch_bounds__(128) void colstat_k(
    const __half* __restrict__ s, float* __restrict__ pm, float* __restrict__ ps)
{
    int j  = blockIdx.x * 128 + threadIdx.x;
    int z  = blockIdx.z;
    int i0 = blockIdx.y * ROWS_PER_CHUNK;
    const __half* p = s + (size_t)z * SS * SS + (size_t)i0 * SS + j;
    float m = -1e30f, l = 0.0f;
    #pragma unroll 4
    for (int i = 0; i < ROWS_PER_CHUNK; i++) {
        float v = __half2float(p[(size_t)i * SS]);
        if (v <= m) {
            l += fexp(v - m);
        } else {
            l = l * fexp(m - v) + 1.0f;
            m = v;
        }
    }
    size_t o = ((size_t)blockIdx.y * BB + z) * SS + j;
    pm[o] = m;
    ps[o] = l;
}

__global__ __launch_bounds__(256) void colreduce_k(
    const float* __restrict__ pm, const float* __restrict__ ps,
    float* __restrict__ off)
{
    int idx = blockIdx.x * 256 + threadIdx.x;
    float m = -1e30f;
    #pragma unroll
    for (int c = 0; c < NCHUNK; c++) m = fmaxf(m, pm[(size_t)c * NROWS + idx]);
    float l = 0.0f;
    #pragma unroll
    for (int c = 0; c < NCHUNK; c++)
        l += ps[(size_t)c * NROWS + idx] * fexp(pm[(size_t)c * NROWS + idx] - m);
    off[idx] = m + logf(l);
}

/* ------------------------------- launch ---------------------------------- */
static float* sym(const void* s) {
    void* p = nullptr;
    cudaGetSymbolAddress(&p, s);
    return (float*)p;
}

extern "C" void kernel_launch(void* const* d_in, const int* in_sizes, int n_in,
                              void* d_out, int out_size)
{
    const float* x    = (const float*)d_in[0];
    const float* ln1w = (const float*)d_in[1];
    const float* ln1b = (const float*)d_in[2];
    const float* wq   = (const float*)d_in[3];
    const float* bq   = (const float*)d_in[4];
    const float* wk   = (const float*)d_in[5];
    const float* bk   = (const float*)d_in[6];
    const float* wv   = (const float*)d_in[7];
    const float* bv   = (const float*)d_in[8];
    const float* wo   = (const float*)d_in[9];
    const float* bo   = (const float*)d_in[10];
    const float* ln2w = (const float*)d_in[11];
    const float* ln2b = (const float*)d_in[12];
    const float* w1   = (const float*)d_in[13];
    const float* b1   = (const float*)d_in[14];
    const float* w2   = (const float*)d_in[15];
    const float* b2   = (const float*)d_in[16];
    float* out = (float*)d_out;

    float* pt   = sym(g_t);
    float* pxl  = sym(g_xl);
    float* pq   = sym(g_q);
    float* pk   = sym(g_k);
    float* pv   = sym(g_v);
    float* pvT  = sym(g_vT);
    float* py   = sym(g_y);
    float* pao  = sym(g_ao);
    float* pfin = sym(g_fin);
    float* ph_  = sym(g_h);
    void*  psch = nullptr; cudaGetSymbolAddress(&psch, g_scoresh);
    float* ppm  = sym(g_pm);
    float* pps  = sym(g_ps);
    float* poff = sym(g_off);
    float* pwqT = sym(g_wqT);
    float* pwkT = sym(g_wkT);
    float* pwvT = sym(g_wvT);
    float* pwoT = sym(g_woT);
    float* pw1T = sym(g_w1T);
    float* pw2T = sym(g_w2T);

    cudaFuncSetAttribute(gemm_mma<0,1>, cudaFuncAttributeMaxDynamicSharedMemorySize, GEMM_SMEM);
    cudaFuncSetAttribute(gemm_mma<0,2>, cudaFuncAttributeMaxDynamicSharedMemorySize, GEMM_SMEM);
    cudaFuncSetAttribute(gemm_mma<0,3>, cudaFuncAttributeMaxDynamicSharedMemorySize, GEMM_SMEM);
    cudaFuncSetAttribute(gemm_mma<0,4>, cudaFuncAttributeMaxDynamicSharedMemorySize, GEMM_SMEM);
    cudaFuncSetAttribute(gemm_mma<0,5>, cudaFuncAttributeMaxDynamicSharedMemorySize, GEMM_SMEM);
    cudaFuncSetAttribute(gemm_mma<1,0>, cudaFuncAttributeMaxDynamicSharedMemorySize, GEMM_SMEM);

    dim3 tb(32, 32);
    const long long sSC = (long long)SS * CCH;
    const long long sS2 = (long long)SS * SS;

    /* x [B,C,S] -> t [B,S,C] */
    transpose_k<<<dim3(SS/32, CCH/32, BB), tb>>>(x, pt, CCH, SS);

    /* LN1 */
    ln_k<<<NROWS/8, 256>>>(pt, ln1w, ln1b, pxl);

    /* weight transposes (W[K,N] -> W^T[N,K]) */
    transpose_k<<<dim3(4, 4, 1), tb>>>(wq, pwqT, CCH, CCH);
    transpose_k<<<dim3(4, 4, 1), tb>>>(wk, pwkT, CCH, CCH);
    transpose_k<<<dim3(4, 4, 1), tb>>>(wv, pwvT, CCH, CCH);
    transpose_k<<<dim3(4, 4, 1), tb>>>(wo, pwoT, CCH, CCH);
    transpose_k<<<dim3(8, 4, 1), tb>>>(w1, pw1T, CCH, HIDN);
    transpose_k<<<dim3(4, 8, 1), tb>>>(w2, pw2T, HIDN, CCH);

    /* QKV projections */
    gemm_mma<0,1><<<dim3(1, NROWS/128, 1), 256, GEMM_SMEM>>>(pxl, pwqT, bq, nullptr, pq,
        CCH, CCH, 0, 0, 0, nullptr, 0, 1.0f);
    gemm_mma<0,1><<<dim3(1, NROWS/128, 1), 256, GEMM_SMEM>>>(pxl, pwkT, bk, nullptr, pk,
        CCH, CCH, 0, 0, 0, nullptr, 0, 1.0f);
    gemm_mma<0,1><<<dim3(1, NROWS/128, 1), 256, GEMM_SMEM>>>(pxl, pwvT, bv, nullptr, pv,
        CCH, CCH, 0, 0, 0, nullptr, 0, 1.0f);

    /* scores = 0.25 * q @ k^T -> fp16 */
    gemm_mma<0,5><<<dim3(SS/128, SS/128, BB), 256, GEMM_SMEM>>>(pq, pk, nullptr, nullptr, psch,
        SS, CCH, sSC, sSC, sS2, nullptr, 0, 0.25f);

    /* column softmax stats on fp16 scores */
    colstat_k<<<dim3(SS/128, NCHUNK, BB), 128>>>((const __half*)psch, ppm, pps);
    colreduce_k<<<NROWS/256, 256>>>(ppm, pps, poff);

    /* v -> vT per batch */
    transpose_k<<<dim3(CCH/32, SS/32, BB), tb>>>(pv, pvT, SS, CCH);

    /* ao = exp(scores - off) @ v (half A, exp on tile load) */
    gemm_mma<1,0><<<dim3(1, SS/128, BB), 256, GEMM_SMEM>>>(psch, pvT, nullptr, nullptr, pao,
        CCH, SS, sS2, sSC, sSC, poff, SS, 1.0f);

    /* y = ao @ wo + bo + t */
    gemm_mma<0,2><<<dim3(1, NROWS/128, 1), 256, GEMM_SMEM>>>(pao, pwoT, bo, pt, py,
        CCH, CCH, 0, 0, 0, nullptr, 0, 1.0f);

    /* LN2 */
    ln_k<<<NROWS/8, 256>>>(py, ln2w, ln2b, pxl);

    /* h = gelu(ln2 @ w1 + b1) */
    gemm_mma<0,3><<<dim3(HIDN/128, NROWS/128, 1), 256, GEMM_SMEM>>>(pxl, pw1T, b1, nullptr, ph_,
        HIDN, CCH, 0, 0, 0, nullptr, 0, 1.0f);

    /* fin = gelu(h @ w2 + b2) + y */
    gemm_mma<0,4><<<dim3(1, NROWS/128, 1), 256, GEMM_SMEM>>>(ph_, pw2T, b2, py, pfin,
        CCH, HIDN, 0, 0, 0, nullptr, 0, 1.0f);

    /* fin [B,S,C] -> out [B,C,H,W] */
    transpose_k<<<dim3(CCH/32, SS/32, BB), tb>>>(pfin, out, SS, CCH);
}

// round 7
// speedup vs baseline: 2.5354x; 1.4906x over previous
#include <cuda_runtime.h>
#include <cuda_fp16.h>
#include <math.h>
#include <stdint.h>

#define BB 4
#define SS 4096
#define CCH 128
#define HIDN 256
#define NROWS (BB*SS)      /* 16384 */
#define NCHUNK 16
#define ROWS_PER_CHUNK (SS/NCHUNK)  /* 256 */

/* ------------ scratch (device globals: allocation-free rule) ------------- */
__device__ float  g_t   [NROWS*CCH];
__device__ __half g_xl  [NROWS*CCH];
__device__ __half g_q   [NROWS*CCH];
__device__ __half g_k   [NROWS*CCH];
__device__ __half g_v   [NROWS*CCH];
__device__ __half g_vT  [NROWS*CCH];
__device__ float  g_y   [NROWS*CCH];
__device__ __half g_ao  [NROWS*CCH];
__device__ float  g_fin [NROWS*CCH];
__device__ __half g_h   [NROWS*HIDN];
__device__ __half g_scoresh[(size_t)BB*SS*SS];   /* 134 MB fp16 scores */
__device__ float  g_pm  [NCHUNK*NROWS];
__device__ float  g_ps  [NCHUNK*NROWS];
__device__ float  g_off [NROWS];
__device__ __half g_wqT [CCH*CCH];
__device__ __half g_wkT [CCH*CCH];
__device__ __half g_wvT [CCH*CCH];
__device__ __half g_woT [CCH*CCH];
__device__ __half g_w1T [CCH*HIDN];
__device__ __half g_w2T [CCH*HIDN];

/* ------------------------- fast exp (FFMA-only) -------------------------- */
__device__ __forceinline__ float fexp(float x) {
    x = fmaxf(x, -80.0f);
    float t = x * 1.4426950408889634f;
    float k = rintf(t);
    float f = fmaf(k, -0.693359375f, x);
    f = fmaf(k, 2.12194440e-4f, f);
    float p = fmaf(f, 8.3333333e-3f, 4.1666667e-2f);
    p = fmaf(p, f, 1.6666667e-1f);
    p = fmaf(p, f, 5.0e-1f);
    p = fmaf(p, f, 1.0f);
    p = fmaf(p, f, 1.0f);
    int ki = (int)k;
    float sc = __int_as_float((ki + 127) << 23);
    return p * sc;
}

__device__ __forceinline__ float gelu_exact(float v) {
    return 0.5f * v * (1.0f + erff(v * 0.70710678118654752f));
}

/* fp16 mma m16n8k16, fp32 accumulate */
__device__ __forceinline__ void mma_f16(
    float* d, uint32_t a0, uint32_t a1, uint32_t a2, uint32_t a3,
    uint32_t b0, uint32_t b1)
{
    asm volatile(
        "mma.sync.aligned.m16n8k16.row.col.f32.f16.f16.f32 "
        "{%0,%1,%2,%3}, {%4,%5,%6,%7}, {%8,%9}, {%0,%1,%2,%3};"
        : "+f"(d[0]), "+f"(d[1]), "+f"(d[2]), "+f"(d[3])
        : "r"(a0), "r"(a1), "r"(a2), "r"(a3), "r"(b0), "r"(b1));
}

/* --------------------- transposes ---------------------------------------- */
__global__ __launch_bounds__(1024) void transpose_k(
    const float* __restrict__ src, float* __restrict__ dst, int R, int Cc)
{
    __shared__ float tile[32][33];
    size_t zo = (size_t)blockIdx.z * R * Cc;
    int c0 = blockIdx.x * 32, r0 = blockIdx.y * 32;
    int x = threadIdx.x, y = threadIdx.y;
    tile[y][x] = src[zo + (size_t)(r0 + y) * Cc + c0 + x];
    __syncthreads();
    dst[zo + (size_t)(c0 + y) * R + r0 + x] = tile[x][y];
}

/* float in -> half out, transposed */
__global__ __launch_bounds__(1024) void transpose_f2h(
    const float* __restrict__ src, __half* __restrict__ dst, int R, int Cc)
{
    __shared__ float tile[32][33];
    int c0 = blockIdx.x * 32, r0 = blockIdx.y * 32;
    int x = threadIdx.x, y = threadIdx.y;
    tile[y][x] = src[(size_t)(r0 + y) * Cc + c0 + x];
    __syncthreads();
    dst[(size_t)(c0 + y) * R + r0 + x] = __float2half_rn(tile[x][y]);
}

/* half -> half, transposed, per batch */
__global__ __launch_bounds__(1024) void transpose_h(
    const __half* __restrict__ src, __half* __restrict__ dst, int R, int Cc)
{
    __shared__ __half tile[32][34];
    size_t zo = (size_t)blockIdx.z * R * Cc;
    int c0 = blockIdx.x * 32, r0 = blockIdx.y * 32;
    int x = threadIdx.x, y = threadIdx.y;
    tile[y][x] = src[zo + (size_t)(r0 + y) * Cc + c0 + x];
    __syncthreads();
    dst[zo + (size_t)(c0 + y) * R + r0 + x] = tile[x][y];
}

/* ----------------------------- LayerNorm (half out) ---------------------- */
__global__ __launch_bounds__(256) void ln_k(
    const float* __restrict__ in, const float* __restrict__ w,
    const float* __restrict__ b, __half* __restrict__ out)
{
    int row  = blockIdx.x * 8 + (threadIdx.x >> 5);
    int lane = threadIdx.x & 31;
    size_t base = (size_t)row * CCH + lane * 4;
    float4 v = *(const float4*)&in[base];
    float s = v.x + v.y + v.z + v.w;
    #pragma unroll
    for (int o = 16; o > 0; o >>= 1) s += __shfl_xor_sync(0xffffffffu, s, o);
    float mu = s * (1.0f / 128.0f);
    float dx = v.x - mu, dy = v.y - mu, dz = v.z - mu, dw = v.w - mu;
    float q = dx*dx + dy*dy + dz*dz + dw*dw;
    #pragma unroll
    for (int o = 16; o > 0; o >>= 1) q += __shfl_xor_sync(0xffffffffu, q, o);
    float rstd = rsqrtf(q * (1.0f / 128.0f) + 1e-5f);
    float4 wv = *(const float4*)&w[lane * 4];
    float4 bv = *(const float4*)&b[lane * 4];
    __half2 h01 = __floats2half2_rn(dx * rstd * wv.x + bv.x, dy * rstd * wv.y + bv.y);
    __half2 h23 = __floats2half2_rn(dz * rstd * wv.z + bv.z, dw * rstd * wv.w + bv.w);
    uint2 o2; o2.x = *(uint32_t*)&h01; o2.y = *(uint32_t*)&h23;
    *(uint2*)&out[base] = o2;
}

/* ------------------ fp16 mma.sync GEMM: D = A @ B^T ----------------------- */
/* A half row-major [M,K], B half row-major [N,K]. Tile 128x128, BK=32,
 * double-buffered static SMEM ([128][40] halves/buffer: 20-word row stride,
 * conflict-free). 256 threads = 8 warps (4M x 2N); warp tile 32x64; m16n8k16.
 * AMODE: 0 = plain half A; 1 = half A with fexp(a - off[k]).
 * EPI:   0 half out, alpha;        1 half out, +bias;
 *        2 float out, +bias+res;   3 half out, gelu(+bias);
 *        4 float out, gelu(+bias)+res.
 */
#define LDH 40
#define HBUF (128*LDH)

template<int AMODE, int EPI>
__global__ __launch_bounds__(256, 1) void gemm_h(
    const __half* __restrict__ A, const __half* __restrict__ Bm,
    const float* __restrict__ bias, const float* __restrict__ res,
    void* __restrict__ Cout,
    int N, int K,
    long long sA, long long sB, long long sC,
    const float* __restrict__ off, int sOff, float alpha)
{
    __shared__ __half As[2][HBUF];
    __shared__ __half Bs[2][HBUF];

    int t = threadIdx.x;
    int wid = t >> 5, lane = t & 31;
    int wm = wid & 3, wn = wid >> 2;
    int gid = lane >> 2, tig = lane & 3;
    int z = blockIdx.z;
    const __half* Ab = A + (size_t)z * sA;
    const __half* Bb = Bm + (size_t)z * sB;
    const float* Rb = (EPI == 2 || EPI == 4) ? res + (size_t)z * sC : nullptr;
    const float* offb = (AMODE == 1) ? off + (size_t)z * sOff : nullptr;
    int m0 = blockIdx.y * 128;
    int n0 = blockIdx.x * 128;

    float acc[2][8][4];
    #pragma unroll
    for (int mt = 0; mt < 2; mt++)
        #pragma unroll
        for (int nt = 0; nt < 8; nt++)
            #pragma unroll
            for (int e = 0; e < 4; e++) acc[mt][nt][e] = 0.0f;

    int nch = K >> 5;

    /* per-chunk staging regs: each thread handles 2 x 8 halves of A and B */
    uint4 ra[2], rb[2];
    auto ldg_chunk = [&](int c) {
        int k0 = c << 5;
        #pragma unroll
        for (int i = 0; i < 2; i++) {
            int idx = i * 256 + t;          /* 512 segments of 8 halves */
            int r = idx >> 2, c8 = idx & 3;
            uint4 va = *(const uint4*)&Ab[(size_t)(m0 + r) * K + k0 + c8 * 8];
            if (AMODE == 1) {
                int kk = k0 + c8 * 8;
                const __half2* hp = (const __half2*)&va;
                float4 lo, hi;
                lo.x = fexp(__low2float(hp[0])  - __ldg(offb + kk + 0));
                lo.y = fexp(__high2float(hp[0]) - __ldg(offb + kk + 1));
                lo.z = fexp(__low2float(hp[1])  - __ldg(offb + kk + 2));
                lo.w = fexp(__high2float(hp[1]) - __ldg(offb + kk + 3));
                hi.x = fexp(__low2float(hp[2])  - __ldg(offb + kk + 4));
                hi.y = fexp(__high2float(hp[2]) - __ldg(offb + kk + 5));
                hi.z = fexp(__low2float(hp[3])  - __ldg(offb + kk + 6));
                hi.w = fexp(__high2float(hp[3]) - __ldg(offb + kk + 7));
                __half2 p0 = __floats2half2_rn(lo.x, lo.y);
                __half2 p1 = __floats2half2_rn(lo.z, lo.w);
                __half2 p2 = __floats2half2_rn(hi.x, hi.y);
                __half2 p3 = __floats2half2_rn(hi.z, hi.w);
                va.x = *(uint32_t*)&p0; va.y = *(uint32_t*)&p1;
                va.z = *(uint32_t*)&p2; va.w = *(uint32_t*)&p3;
            }
            ra[i] = va;
            rb[i] = *(const uint4*)&Bb[(size_t)(n0 + r) * K + k0 + c8 * 8];
        }
    };
    auto st_chunk = [&](int buf) {
        #pragma unroll
        for (int i = 0; i < 2; i++) {
            int idx = i * 256 + t;
            int r = idx >> 2, c8 = idx & 3;
            *(uint4*)&As[buf][r * LDH + c8 * 8] = ra[i];
            *(uint4*)&Bs[buf][r * LDH + c8 * 8] = rb[i];
        }
    };

    ldg_chunk(0);
    st_chunk(0);
    __syncthreads();

    for (int c = 0; c < nch; c++) {
        if (c + 1 < nch) ldg_chunk(c + 1);
        const __half* Ap = As[c & 1];
        const __half* Bp = Bs[c & 1];
        #pragma unroll
        for (int s = 0; s < 2; s++) {
            int cA = s * 16 + tig * 2;
            uint32_t af[2][4];
            #pragma unroll
            for (int mt = 0; mt < 2; mt++) {
                int ar = wm * 32 + mt * 16 + gid;
                af[mt][0] = *(const uint32_t*)&Ap[ar * LDH + cA];
                af[mt][1] = *(const uint32_t*)&Ap[(ar + 8) * LDH + cA];
                af[mt][2] = *(const uint32_t*)&Ap[ar * LDH + cA + 8];
                af[mt][3] = *(const uint32_t*)&Ap[(ar + 8) * LDH + cA + 8];
            }
            #pragma unroll
            for (int nt = 0; nt < 8; nt++) {
                int bn = wn * 64 + nt * 8 + gid;
                uint32_t b0 = *(const uint32_t*)&Bp[bn * LDH + cA];
                uint32_t b1 = *(const uint32_t*)&Bp[bn * LDH + cA + 8];
                #pragma unroll
                for (int mt = 0; mt < 2; mt++)
                    mma_f16(acc[mt][nt],
                            af[mt][0], af[mt][1], af[mt][2], af[mt][3], b0, b1);
            }
        }
        if (c + 1 < nch) {
            st_chunk((c + 1) & 1);
            __syncthreads();
        }
    }

    /* ------------------------------ epilogue ----------------------------- */
    int rbase = m0 + wm * 32 + gid;
    int cbase = n0 + wn * 64 + tig * 2;

    if (EPI == 0 || EPI == 1 || EPI == 3) {
        __half* Cb = (__half*)Cout + (size_t)z * sC;
        #pragma unroll
        for (int mt = 0; mt < 2; mt++) {
            #pragma unroll
            for (int hh = 0; hh < 2; hh++) {
                int row = rbase + mt * 16 + hh * 8;
                size_t rowo = (size_t)row * N;
                #pragma unroll
                for (int nt = 0; nt < 8; nt++) {
                    int col = cbase + nt * 8;
                    float u0 = acc[mt][nt][hh * 2 + 0] * alpha;
                    float u1 = acc[mt][nt][hh * 2 + 1] * alpha;
                    if (EPI == 1 || EPI == 3) {
                        u0 += __ldg(&bias[col]);
                        u1 += __ldg(&bias[col + 1]);
                    }
                    if (EPI == 3) {
                        u0 = gelu_exact(u0);
                        u1 = gelu_exact(u1);
                    }
                    __half2 h2 = __floats2half2_rn(u0, u1);
                    *(__half2*)&Cb[rowo + col] = h2;
                }
            }
        }
        return;
    }

    float* Cb = (float*)Cout + (size_t)z * sC;
    #pragma unroll
    for (int mt = 0; mt < 2; mt++) {
        #pragma unroll
        for (int hh = 0; hh < 2; hh++) {
            int row = rbase + mt * 16 + hh * 8;
            size_t rowo = (size_t)row * N;
            #pragma unroll
            for (int nt = 0; nt < 8; nt++) {
                int col = cbase + nt * 8;
                float u0 = acc[mt][nt][hh * 2 + 0] * alpha + __ldg(&bias[col]);
                float u1 = acc[mt][nt][hh * 2 + 1] * alpha + __ldg(&bias[col + 1]);
                if (EPI == 4) {
                    u0 = gelu_exact(u0);
                    u1 = gelu_exact(u1);
                }
                u0 += Rb[rowo + col];
                u1 += Rb[rowo + col + 1];
                float2 o2; o2.x = u0; o2.y = u1;
                *(float2*)&Cb[rowo + col] = o2;
            }
        }
    }
}

/* ------------- column (query-axis) softmax stats on fp16 scores ---------- */
__global__ __launch_bounds__(128) void colstat_k(
    const __half* __restrict__ s, float* __restrict__ pm, float* __restrict__ ps)
{
    int j  = blockIdx.x * 128 + threadIdx.x;
    int z  = blockIdx.z;
    int i0 = blockIdx.y * ROWS_PER_CHUNK;
    const __half* p = s + (size_t)z * SS * SS + (size_t)i0 * SS + j;
    float m = -1e30f, l = 0.0f;
    #pragma unroll 4
    for (int i = 0; i < ROWS_PER_CHUNK; i++) {
        float v = __half2float(p[(size_t)i * SS]);
        if (v <= m) {
            l += fexp(v - m);
        } else {
            l = l * fexp(m - v) + 1.0f;
            m = v;
        }
    }
    size_t o = ((size_t)blockIdx.y * BB + z) * SS + j;
    pm[o] = m;
    ps[o] = l;
}

__global__ __launch_bounds__(256) void colreduce_k(
    const float* __restrict__ pm, const float* __restrict__ ps,
    float* __restrict__ off)
{
    int idx = blockIdx.x * 256 + threadIdx.x;
    float m = -1e30f;
    #pragma unroll
    for (int c = 0; c < NCHUNK; c++) m = fmaxf(m, pm[(size_t)c * NROWS + idx]);
    float l = 0.0f;
    #pragma unroll
    for (int c = 0; c < NCHUNK; c++)
        l += ps[(size_t)c * NROWS + idx] * fexp(pm[(size_t)c * NROWS + idx] - m);
    off[idx] = m + logf(l);
}

/* ------------------------------- launch ---------------------------------- */
template<typename T>
static T* symp(const void* s) {
    void* p = nullptr;
    cudaGetSymbolAddress(&p, s);
    return (T*)p;
}

extern "C" void kernel_launch(void* const* d_in, const int* in_sizes, int n_in,
                              void* d_out, int out_size)
{
    const float* x    = (const float*)d_in[0];
    const float* ln1w = (const float*)d_in[1];
    const float* ln1b = (const float*)d_in[2];
    const float* wq   = (const float*)d_in[3];
    const float* bq   = (const float*)d_in[4];
    const float* wk   = (const float*)d_in[5];
    const float* bk   = (const float*)d_in[6];
    const float* wv   = (const float*)d_in[7];
    const float* bv   = (const float*)d_in[8];
    const float* wo   = (const float*)d_in[9];
    const float* bo   = (const float*)d_in[10];
    const float* ln2w = (const float*)d_in[11];
    const float* ln2b = (const float*)d_in[12];
    const float* w1   = (const float*)d_in[13];
    const float* b1   = (const float*)d_in[14];
    const float* w2   = (const float*)d_in[15];
    const float* b2   = (const float*)d_in[16];
    float* out = (float*)d_out;

    float*  pt   = symp<float>(g_t);
    __half* pxl  = symp<__half>(g_xl);
    __half* pq   = symp<__half>(g_q);
    __half* pk   = symp<__half>(g_k);
    __half* pv   = symp<__half>(g_v);
    __half* pvT  = symp<__half>(g_vT);
    float*  py   = symp<float>(g_y);
    __half* pao  = symp<__half>(g_ao);
    float*  pfin = symp<float>(g_fin);
    __half* ph_  = symp<__half>(g_h);
    __half* psch = symp<__half>(g_scoresh);
    float*  ppm  = symp<float>(g_pm);
    float*  pps  = symp<float>(g_ps);
    float*  poff = symp<float>(g_off);
    __half* pwqT = symp<__half>(g_wqT);
    __half* pwkT = symp<__half>(g_wkT);
    __half* pwvT = symp<__half>(g_wvT);
    __half* pwoT = symp<__half>(g_woT);
    __half* pw1T = symp<__half>(g_w1T);
    __half* pw2T = symp<__half>(g_w2T);

    dim3 tb(32, 32);
    const long long sSC = (long long)SS * CCH;
    const long long sS2 = (long long)SS * SS;

    /* x [B,C,S] -> t [B,S,C] */
    transpose_k<<<dim3(SS/32, CCH/32, BB), tb>>>(x, pt, CCH, SS);

    /* LN1 -> half */
    ln_k<<<NROWS/8, 256>>>(pt, ln1w, ln1b, pxl);

    /* weight transposes+convert (W[K,N] -> W^T[N,K] half) */
    transpose_f2h<<<dim3(4, 4, 1), tb>>>(wq, pwqT, CCH, CCH);
    transpose_f2h<<<dim3(4, 4, 1), tb>>>(wk, pwkT, CCH, CCH);
    transpose_f2h<<<dim3(4, 4, 1), tb>>>(wv, pwvT, CCH, CCH);
    transpose_f2h<<<dim3(4, 4, 1), tb>>>(wo, pwoT, CCH, CCH);
    transpose_f2h<<<dim3(8, 4, 1), tb>>>(w1, pw1T, CCH, HIDN);
    transpose_f2h<<<dim3(4, 8, 1), tb>>>(w2, pw2T, HIDN, CCH);

    /* QKV projections -> half */
    gemm_h<0,1><<<dim3(1, NROWS/128, 1), 256>>>(pxl, pwqT, bq, nullptr, pq,
        CCH, CCH, 0, 0, 0, nullptr, 0, 1.0f);
    gemm_h<0,1><<<dim3(1, NROWS/128, 1), 256>>>(pxl, pwkT, bk, nullptr, pk,
        CCH, CCH, 0, 0, 0, nullptr, 0, 1.0f);
    gemm_h<0,1><<<dim3(1, NROWS/128, 1), 256>>>(pxl, pwvT, bv, nullptr, pv,
        CCH, CCH, 0, 0, 0, nullptr, 0, 1.0f);

    /* scores = 0.25 * q @ k^T -> fp16 */
    gemm_h<0,0><<<dim3(SS/128, SS/128, BB), 256>>>(pq, pk, nullptr, nullptr, psch,
        SS, CCH, sSC, sSC, sS2, nullptr, 0, 0.25f);

    /* column softmax stats on fp16 scores */
    colstat_k<<<dim3(SS/128, NCHUNK, BB), 128>>>(psch, ppm, pps);
    colreduce_k<<<NROWS/256, 256>>>(ppm, pps, poff);

    /* v -> vT per batch (half) */
    transpose_h<<<dim3(CCH/32, SS/32, BB), tb>>>(pv, pvT, SS, CCH);

    /* ao = exp(scores - off) @ v -> half */
    gemm_h<1,0><<<dim3(1, SS/128, BB), 256>>>(psch, pvT, nullptr, nullptr, pao,
        CCH, SS, sS2, sSC, sSC, poff, SS, 1.0f);

    /* y = ao @ wo + bo + t (float) */
    gemm_h<0,2><<<dim3(1, NROWS/128, 1), 256>>>(pao, pwoT, bo, pt, py,
        CCH, CCH, 0, 0, 0, nullptr, 0, 1.0f);

    /* LN2 -> half */
    ln_k<<<NROWS/8, 256>>>(py, ln2w, ln2b, pxl);

    /* h = gelu(ln2 @ w1 + b1) -> half */
    gemm_h<0,3><<<dim3(HIDN/128, NROWS/128, 1), 256>>>(pxl, pw1T, b1, nullptr, ph_,
        HIDN, CCH, 0, 0, 0, nullptr, 0, 1.0f);

    /* fin = gelu(h @ w2 + b2) + y (float) */
    gemm_h<0,4><<<dim3(1, NROWS/128, 1), 256>>>(ph_, pw2T, b2, py, pfin,
        CCH, HIDN, 0, 0, 0, nullptr, 0, 1.0f);

    /* fin [B,S,C] -> out [B,C,H,W] */
    transpose_k<<<dim3(CCH/32, SS/32, BB), tb>>>(pfin, out, SS, CCH);
}